// round 17
// baseline (speedup 1.0000x reference)
#include <cuda_runtime.h>
#include <math.h>

// ---------------------------------------------------------------------------
// CMAF fused block, round 17 = round 16 + generic path converted to BK=32
// stages (3 buffers, prefetch distance 2): barriers halved on spatial/gf/
// outproj/ffn2, two tile_mma per sync window. Resident path unchanged (R16).
// ---------------------------------------------------------------------------

#define MAXB 65536
#define CHW 2048                         // words per 16-k chunk (128 rows x 16)
#define SGW (4 * CHW)                    // words per 32-k stage (A0,A1,W0,W1)
#define GSMEM (3 * SGW * 4)              // 98304 B (generic path, 3 stages)

#define AFP2 144                         // resident-A row stride (=16 mod 32)
#define QW2 (128 * AFP2)                 // words
#define WSTG 4096                        // words per 32-k W stage (2 chunks)
#define QSMEM ((QW2 + 2 * WSTG) * 4)     // 106496 B (resident path)

__device__ __align__(16) float g_P [MAXB * 3 * 128];
__device__ __align__(16) float g_q [MAXB * 3 * 128];
__device__ __align__(16) float g_k [MAXB * 6 * 128];
__device__ __align__(16) float g_v [MAXB * 6 * 128];
__device__ __align__(16) float g_o [MAXB * 3 * 128];
__device__ __align__(16) float g_x1[MAXB * 3 * 128];
__device__ __align__(16) float g_h [MAXB * 3 * 256];
__device__ __align__(16) float g_x2[MAXB * 3 * 128];

// tf32-preconverted weights (contiguous: spatial|gf|inw|outw|ffn1|ffn2)
#define WOFF_SPATIAL 0
#define WOFF_GF      163840
#define WOFF_INW     196608
#define WOFF_OUTW    344064
#define WOFF_FFN1    393216
#define WOFF_FFN2    491520
__device__ __align__(16) float g_wtf[589824];

// QKV jobs per source stream s: {w_off (within in_w), b_off, buf_id, out_off}
__constant__ int qkv_jobs[3][5][4] = {
    { {     0,    0, 0,   0}, { 65536,  512, 1, 256}, { 81920,  640, 2, 256},
      {114688,  896, 1, 512}, {131072, 1024, 2, 512} },
    { { 49152,  384, 0, 128}, { 16384,  128, 1,   0}, { 32768,  256, 2,   0},
      {114688,  896, 1, 640}, {131072, 1024, 2, 640} },
    { { 98304,  768, 0, 256}, { 16384,  128, 1, 128}, { 32768,  256, 2, 128},
      { 65536,  512, 1, 384}, { 81920,  640, 2, 384} },
};

__device__ __forceinline__ unsigned f2tf(float f) {
    unsigned u;
    asm("cvt.rna.tf32.f32 %0, %1;" : "=r"(u) : "f"(f));
    return u;
}
__device__ __forceinline__ float tfr(float f) {
    return __uint_as_float(f2tf(f));
}
__device__ __forceinline__ unsigned fau(float f) { return __float_as_uint(f); }

__device__ __forceinline__ void mma8(float c[4], const unsigned a[4], const unsigned b[2]) {
    asm volatile(
        "mma.sync.aligned.m16n8k8.row.col.f32.tf32.tf32.f32 "
        "{%0,%1,%2,%3}, {%4,%5,%6,%7}, {%8,%9}, {%0,%1,%2,%3};\n"
        : "+f"(c[0]), "+f"(c[1]), "+f"(c[2]), "+f"(c[3])
        : "r"(a[0]), "r"(a[1]), "r"(a[2]), "r"(a[3]), "r"(b[0]), "r"(b[1]));
}

__device__ __forceinline__ void cp16(unsigned smem_dst, const void* gsrc) {
    asm volatile("cp.async.cg.shared.global [%0], [%1], 16;\n"
                 :: "r"(smem_dst), "l"(gsrc));
}
__device__ __forceinline__ void cp_commit() {
    asm volatile("cp.async.commit_group;\n");
}
template <int N>
__device__ __forceinline__ void cp_wait() {
    asm volatile("cp.async.wait_group %0;\n" :: "n"(N));
}

// ---------------------------------------------------------------------------
// Epilogue. EPI: 0=bias, 1=bias+gelu, 2=bias+LN+addv, 3=bias+resid+LN
// RND: store tf32-rounded.
// ---------------------------------------------------------------------------
template <int EPI, int RND>
__device__ __forceinline__ void epi_store(
    float acc[4][4][4],
    const float* __restrict__ bias,
    const float* __restrict__ lng, const float* __restrict__ lnb,
    const float* __restrict__ addv,
    const float* __restrict__ resid, int rstride,
    float* __restrict__ out, int ostride, int m0, int M)
{
    __shared__ float2 pbuf[128][4];
    const int tid = threadIdx.x, wid = tid >> 5, lane = tid & 31;
    const int wm = (wid & 1) * 64, wn = (wid >> 1) * 32, wq = wid >> 1;
    const int g = lane >> 2, t4 = lane & 3;

    float b2[4][2];
#pragma unroll
    for (int nt = 0; nt < 4; ++nt) {
        const int col = wn + nt * 8 + t4 * 2;
        b2[nt][0] = bias[col]; b2[nt][1] = bias[col + 1];
    }

    if (EPI <= 1) {
#pragma unroll
        for (int mt = 0; mt < 4; ++mt)
#pragma unroll
        for (int hf = 0; hf < 2; ++hf) {
            const int r = m0 + wm + mt * 16 + hf * 8 + g;
            if (r < M) {
                float* orow = out + (long)r * ostride;
#pragma unroll
                for (int nt = 0; nt < 4; ++nt) {
                    const int col = wn + nt * 8 + t4 * 2;
                    float c0 = acc[mt][nt][hf * 2 + 0] + b2[nt][0];
                    float c1 = acc[mt][nt][hf * 2 + 1] + b2[nt][1];
                    if (EPI == 1) {
                        c0 = c0 * 0.5f * (1.0f + erff(c0 * 0.70710678118654752f));
                        c1 = c1 * 0.5f * (1.0f + erff(c1 * 0.70710678118654752f));
                    }
                    if (RND) { c0 = tfr(c0); c1 = tfr(c1); }
                    *(float2*)(orow + col) = make_float2(c0, c1);
                }
            }
        }
        return;
    }

    // LN path
#pragma unroll
    for (int mt = 0; mt < 4; ++mt)
#pragma unroll
    for (int hf = 0; hf < 2; ++hf) {
        const int lr = wm + mt * 16 + hf * 8 + g;
        const int r  = m0 + lr;
        float s = 0.f, s2 = 0.f;
        const float* rrow = (EPI == 3) ? resid + (long)min(r, M - 1) * rstride : (const float*)0;
#pragma unroll
        for (int nt = 0; nt < 4; ++nt) {
            const int col = wn + nt * 8 + t4 * 2;
            float c0 = acc[mt][nt][hf * 2 + 0] + b2[nt][0];
            float c1 = acc[mt][nt][hf * 2 + 1] + b2[nt][1];
            if (EPI == 3) {
                const float2 rv = *(const float2*)(rrow + col);
                c0 += rv.x; c1 += rv.y;
            }
            acc[mt][nt][hf * 2 + 0] = c0; acc[mt][nt][hf * 2 + 1] = c1;
            s += c0 + c1; s2 += c0 * c0 + c1 * c1;
        }
        s  += __shfl_xor_sync(0xffffffffu, s, 1);
        s  += __shfl_xor_sync(0xffffffffu, s, 2);
        s2 += __shfl_xor_sync(0xffffffffu, s2, 1);
        s2 += __shfl_xor_sync(0xffffffffu, s2, 2);
        if (t4 == 0) pbuf[lr][wq] = make_float2(s, s2);
    }
    __syncthreads();
#pragma unroll
    for (int mt = 0; mt < 4; ++mt)
#pragma unroll
    for (int hf = 0; hf < 2; ++hf) {
        const int lr = wm + mt * 16 + hf * 8 + g;
        const int r  = m0 + lr;
        const float2 p0 = pbuf[lr][0], p1 = pbuf[lr][1], p2 = pbuf[lr][2], p3 = pbuf[lr][3];
        const float s    = p0.x + p1.x + p2.x + p3.x;
        const float s2   = p0.y + p1.y + p2.y + p3.y;
        const float mean = s * 0.0078125f;
        const float var  = s2 * 0.0078125f - mean * mean;
        const float rs   = rsqrtf(var + 1e-5f);
        if (r < M) {
            float* orow = out + (long)r * ostride;
#pragma unroll
            for (int nt = 0; nt < 4; ++nt) {
                const int col = wn + nt * 8 + t4 * 2;
                float o0 = (acc[mt][nt][hf * 2 + 0] - mean) * rs * lng[col]     + lnb[col];
                float o1 = (acc[mt][nt][hf * 2 + 1] - mean) * rs * lng[col + 1] + lnb[col + 1];
                if (EPI == 2) { o0 += addv[col]; o1 += addv[col + 1]; }
                if (RND) { o0 = tfr(o0); o1 = tfr(o1); }
                *(float2*)(orow + col) = make_float2(o0, o1);
            }
        }
    }
}

// inner compute for one 16-k tile (LDS.128 fragments, RAW-spaced issue)
__device__ __forceinline__ void tile_mma(
    const float* __restrict__ smem, int Ab, int Astride, int Akb,
    int Wb, int wm, int wn, int g, int tq, float acc[4][4][4])
{
    float4 bf4[4];
#pragma unroll
    for (int nt = 0; nt < 4; ++nt)
        bf4[nt] = *(const float4*)&smem[Wb + (wn + nt * 8 + g) * 16 + tq];
#pragma unroll
    for (int mt = 0; mt < 4; ++mt) {
        const int r = wm + mt * 16 + g;
        const float4 a0 = *(const float4*)&smem[Ab + r * Astride + Akb + tq];
        const float4 a1 = *(const float4*)&smem[Ab + (r + 8) * Astride + Akb + tq];
        const unsigned aa0[4] = {fau(a0.x), fau(a1.x), fau(a0.y), fau(a1.y)};
        const unsigned aa1[4] = {fau(a0.z), fau(a1.z), fau(a0.w), fau(a1.w)};
#pragma unroll
        for (int nt = 0; nt < 4; ++nt) {
            const unsigned b0[2] = {fau(bf4[nt].x), fau(bf4[nt].y)};
            mma8(acc[mt][nt], aa0, b0);
        }
#pragma unroll
        for (int nt = 0; nt < 4; ++nt) {
            const unsigned b1[2] = {fau(bf4[nt].z), fau(bf4[nt].w)};
            mma8(acc[mt][nt], aa1, b1);
        }
    }
}

// ---------------------------------------------------------------------------
// Generic GEMM core: BK=32 stages, 3 buffers, prefetch distance 2, swizzled
// 16-word chunk rows, LDS.128 frags. Stage layout (words, per stage s):
//   s*SGW + 0      : A chunk0   s*SGW + CHW   : A chunk1
//   s*SGW + 2*CHW  : W chunk0   s*SGW + 3*CHW : W chunk1
// CVTST=1: A staged via LDG+cvt+STS one stage ahead; CVTST=0: A via cp.async.
// Requires K % 32 == 0.
// ---------------------------------------------------------------------------
template <int EPI, int RND, int CVTST>
__device__ __forceinline__ void mma_gemm(
    const float* __restrict__ A, int lda,
    const float* __restrict__ W, int K,
    const float* __restrict__ bias,
    const float* __restrict__ lng, const float* __restrict__ lnb,
    const float* __restrict__ addv,
    const float* __restrict__ resid, int rstride,
    float* __restrict__ out, int ostride,
    int m0, int M)
{
    extern __shared__ float smem[];
    __syncthreads();

    const int tid   = threadIdx.x;
    const int ldRow = tid >> 1;
    const int ldCol = (tid & 1) * 8;
    const int c0    = ldCol >> 2;
    const int rsw   = ldRow & 3;

    const float* Aptr = A + (long)min(m0 + ldRow, M - 1) * lda + ldCol;
    const float* Wptr = W + (long)ldRow * K + ldCol;

    const unsigned sb = (unsigned)__cvta_generic_to_shared(smem);
    // byte offsets of this thread's two store quads within a 16-k chunk
    const unsigned q0 = (unsigned)((ldRow * 16 + ((c0    ) ^ rsw) * 4) * 4);
    const unsigned q1 = (unsigned)((ldRow * 16 + ((c0 + 1) ^ rsw) * 4) * 4);
    const int d0off = ldRow * 16 + ((c0    ) ^ rsw) * 4;   // word offsets (CVTST)
    const int d1off = ldRow * 16 + ((c0 + 1) ^ rsw) * 4;

    const int wid = tid >> 5, lane = tid & 31;
    const int wm = (wid & 1) * 64, wn = (wid >> 1) * 32;
    const int g = lane >> 2, t4 = lane & 3;
    const int tq = (t4 ^ (g & 3)) * 4;

    float acc[4][4][4] = {};
    const int nst = K >> 5;    // 32-k stages

    float4 rg[4];              // CVTST prefetch regs (one full stage of A)
    if (CVTST) {
        // stage 0: direct cvt-store (both chunks)
#pragma unroll
        for (int c = 0; c < 2; ++c) {
            const float4 va = *(const float4*)(Aptr + c * 16);
            const float4 vb = *(const float4*)(Aptr + c * 16 + 4);
            *(float4*)&smem[c * CHW + d0off] =
                make_float4(tfr(va.x), tfr(va.y), tfr(va.z), tfr(va.w));
            *(float4*)&smem[c * CHW + d1off] =
                make_float4(tfr(vb.x), tfr(vb.y), tfr(vb.z), tfr(vb.w));
        }
        if (nst > 1) {      // regs for stage 1
#pragma unroll
            for (int c = 0; c < 2; ++c) {
                rg[c * 2 + 0] = *(const float4*)(Aptr + 32 + c * 16);
                rg[c * 2 + 1] = *(const float4*)(Aptr + 32 + c * 16 + 4);
            }
        }
        // W stages 0,1 (one commit group per stage)
#pragma unroll
        for (int p = 0; p < 2; ++p) {
            if (p < nst) {
                const unsigned wb = sb + (p * SGW + 2 * CHW) * 4;
#pragma unroll
                for (int c = 0; c < 2; ++c) {
                    cp16(wb + c * CHW * 4 + q0, Wptr + p * 32 + c * 16);
                    cp16(wb + c * CHW * 4 + q1, Wptr + p * 32 + c * 16 + 4);
                }
                cp_commit();
            }
        }
    } else {
#pragma unroll
        for (int p = 0; p < 2; ++p) {
            if (p < nst) {
                const unsigned ab = sb + (p * SGW) * 4;
                const unsigned wb = sb + (p * SGW + 2 * CHW) * 4;
#pragma unroll
                for (int c = 0; c < 2; ++c) {
                    cp16(ab + c * CHW * 4 + q0, Aptr + p * 32 + c * 16);
                    cp16(ab + c * CHW * 4 + q1, Aptr + p * 32 + c * 16 + 4);
                    cp16(wb + c * CHW * 4 + q0, Wptr + p * 32 + c * 16);
                    cp16(wb + c * CHW * 4 + q1, Wptr + p * 32 + c * 16 + 4);
                }
                cp_commit();
            }
        }
    }

    int cur = 0;
#pragma unroll 1
    for (int st = 0; st < nst; ++st) {
        if (st + 1 < nst) cp_wait<1>(); else cp_wait<0>();
        __syncthreads();

        if (st + 2 < nst) {
            const int buf = cur + 2 >= 3 ? cur - 1 : cur + 2;
            const int k0 = (st + 2) * 32;
            const unsigned ab = sb + (buf * SGW) * 4;
            const unsigned wb = sb + (buf * SGW + 2 * CHW) * 4;
#pragma unroll
            for (int c = 0; c < 2; ++c) {
                if (!CVTST) {
                    cp16(ab + c * CHW * 4 + q0, Aptr + k0 + c * 16);
                    cp16(ab + c * CHW * 4 + q1, Aptr + k0 + c * 16 + 4);
                }
                cp16(wb + c * CHW * 4 + q0, Wptr + k0 + c * 16);
                cp16(wb + c * CHW * 4 + q1, Wptr + k0 + c * 16 + 4);
            }
            cp_commit();
        }

        if (CVTST) {
            if (st + 1 < nst) {   // store A stage st+1 from regs
                const int nb = cur + 1 >= 3 ? 0 : cur + 1;
#pragma unroll
                for (int c = 0; c < 2; ++c) {
                    const float4 va = rg[c * 2 + 0], vb = rg[c * 2 + 1];
                    *(float4*)&smem[nb * SGW + c * CHW + d0off] =
                        make_float4(tfr(va.x), tfr(va.y), tfr(va.z), tfr(va.w));
                    *(float4*)&smem[nb * SGW + c * CHW + d1off] =
                        make_float4(tfr(vb.x), tfr(vb.y), tfr(vb.z), tfr(vb.w));
                }
            }
            if (st + 2 < nst) {   // regs for stage st+2
                const int k0 = (st + 2) * 32;
#pragma unroll
                for (int c = 0; c < 2; ++c) {
                    rg[c * 2 + 0] = *(const float4*)(Aptr + k0 + c * 16);
                    rg[c * 2 + 1] = *(const float4*)(Aptr + k0 + c * 16 + 4);
                }
            }
        }

        tile_mma(smem, cur * SGW,           16, 0, cur * SGW + 2 * CHW, wm, wn, g, tq, acc);
        tile_mma(smem, cur * SGW + CHW,     16, 0, cur * SGW + 3 * CHW, wm, wn, g, tq, acc);
        cur = cur + 1 >= 3 ? 0 : cur + 1;
    }

    epi_store<EPI, RND>(acc, bias, lng, lnb, addv, resid, rstride, out, ostride, m0, M);
}

// ---------------------------------------------------------------------------
// Resident-A runner (K=128, NJ jobs sharing A), BK=32 stages, 2 W buffers.
// (unchanged from R16)
// ---------------------------------------------------------------------------
template <int NJ, int EPI, int RND>
__device__ __forceinline__ void resA_run(
    const float* __restrict__ A, int lda, int m0, int M,
    const float* const* Wj, const float* const* bj,
    float* const* oj, const int* osj)
{
    extern __shared__ float smem[];
    const int tid = threadIdx.x;
    const int ldRow = tid >> 1, hh = tid & 1;
    const int rsw = ldRow & 3;
    const unsigned sb = (unsigned)__cvta_generic_to_shared(smem);

    // stage A (128x128 raw tf32) into swizzled Af[128][AFP2]
    {
        const float* Ap = A + (long)min(m0 + ldRow, M - 1) * lda + hh * 64;
#pragma unroll
        for (int j = 0; j < 16; ++j) {
            const int b  = hh * 4 + (j >> 2);
            const int qn = (j & 3) ^ rsw;
            cp16(sb + (ldRow * AFP2 + b * 16 + qn * 4) * 4, Ap + 4 * j);
        }
    }
    const int c0 = hh * 2;
    const unsigned wo0 = (unsigned)((ldRow * 16 + ((c0    ) ^ rsw) * 4) * 4);
    const unsigned wo1 = (unsigned)((ldRow * 16 + ((c0 + 1) ^ rsw) * 4) * 4);
    const unsigned wbase = sb + QW2 * 4;

    {
        const float* wp = Wj[0] + (long)ldRow * 128 + hh * 8;
        cp16(wbase + wo0, wp);
        cp16(wbase + wo1, wp + 4);
        cp16(wbase + CHW * 4 + wo0, wp + 16);
        cp16(wbase + CHW * 4 + wo1, wp + 20);
        cp_commit();
    }

    const int wid = tid >> 5, lane = tid & 31;
    const int wm = (wid & 1) * 64, wn = (wid >> 1) * 32;
    const int g = lane >> 2, t4 = lane & 3;
    const int tq = (t4 ^ (g & 3)) * 4;
    const int NTS = NJ * 4;

    float acc[4][4][4] = {};

#pragma unroll 1
    for (int st = 0; st < NTS; ++st) {
        cp_wait<0>();
        __syncthreads();

        if (st + 1 < NTS) {
            const int pj = (st + 1) >> 2, ps = (st + 1) & 3;
            const float* wp = Wj[pj] + (long)ldRow * 128 + ps * 32 + hh * 8;
            const unsigned bs = wbase + ((st + 1) & 1) * WSTG * 4;
            cp16(bs + wo0, wp);
            cp16(bs + wo1, wp + 4);
            cp16(bs + CHW * 4 + wo0, wp + 16);
            cp16(bs + CHW * 4 + wo1, wp + 20);
            cp_commit();
        }

        const int akb = (st & 3) * 32;
        const int wb  = QW2 + (st & 1) * WSTG;
        tile_mma(smem, 0, AFP2, akb,      wb,       wm, wn, g, tq, acc);
        tile_mma(smem, 0, AFP2, akb + 16, wb + CHW, wm, wn, g, tq, acc);

        if ((st & 3) == 3) {
            const int j = st >> 2;
            epi_store<EPI, RND>(acc, bj[j], nullptr, nullptr, nullptr, nullptr, 0,
                                oj[j], osj[j], m0, M);
#pragma unroll
            for (int a = 0; a < 4; ++a)
#pragma unroll
                for (int b = 0; b < 4; ++b)
#pragma unroll
                    for (int c = 0; c < 4; ++c) acc[a][b][c] = 0.f;
        }
    }
}

// ---------------- kernels ----------------

// merged spatial + gf: y=0 -> spatial (K=1280), y=1,2 -> gf stream y-1
__global__ __launch_bounds__(256, 2) void k_g_proj(
    const float* __restrict__ Xs, const float* __restrict__ Xg,
    const float* __restrict__ Xf,
    const float* __restrict__ pb, const float* __restrict__ lng,
    const float* __restrict__ lnb, const float* __restrict__ mod, int M)
{
    const int y = blockIdx.y;
    if (y == 0) {
        mma_gemm<2, 1, 1>(Xs, 1280, g_wtf + WOFF_SPATIAL, 1280, pb, lng, lnb, mod,
                          nullptr, 0, g_P, 384, blockIdx.x * 128, M);
    } else {
        const int s = y - 1, n = y;
        mma_gemm<2, 1, 1>(s ? Xf : Xg, 128, g_wtf + WOFF_GF + s * 128 * 128, 128,
                          pb + n * 128, lng + n * 128, lnb + n * 128, mod + n * 128,
                          nullptr, 0, g_P + n * 128, 384, blockIdx.x * 128, M);
    }
}

__global__ __launch_bounds__(256, 2) void k_g_qkv(
    const float* __restrict__ Bi, int M)
{
    const int s  = blockIdx.y;
    const int m0 = blockIdx.x * 128;
    float* bufs[3] = {g_q, g_k, g_v};
    const float* Wj[5]; const float* bj[5]; float* oj[5]; int osj[5];
#pragma unroll
    for (int j = 0; j < 5; ++j) {
        Wj[j]  = g_wtf + WOFF_INW + qkv_jobs[s][j][0];
        bj[j]  = Bi + qkv_jobs[s][j][1];
        const int bid = qkv_jobs[s][j][2];
        oj[j]  = bufs[bid] + qkv_jobs[s][j][3];
        osj[j] = (bid == 0) ? 384 : 768;
    }
    resA_run<5, 0, 0>(g_P + s * 128, 384, m0, M, Wj, bj, oj, osj);
}

__global__ __launch_bounds__(256, 2) void k_g_outproj(
    const float* __restrict__ bo,
    const float* __restrict__ ag, const float* __restrict__ ab, int M)
{
    const int n = blockIdx.y;
    mma_gemm<3, 1, 0>(g_o + n * 128, 384, g_wtf + WOFF_OUTW + n * 128 * 128, 128,
                      bo + n * 128, ag + n * 128, ab + n * 128, nullptr,
                      g_P + n * 128, 384, g_x1 + n * 128, 384, blockIdx.x * 128, M);
}

__global__ __launch_bounds__(256, 2) void k_g_ffn1(
    const float* __restrict__ B1, int M)
{
    const int n  = blockIdx.y;
    const int m0 = blockIdx.x * 128;
    const float* Wj[2] = { g_wtf + WOFF_FFN1 + n * 32768,
                           g_wtf + WOFF_FFN1 + n * 32768 + 16384 };
    const float* bj[2] = { B1 + n * 256, B1 + n * 256 + 128 };
    float* oj[2] = { g_h + n * 256, g_h + n * 256 + 128 };
    int osj[2] = { 768, 768 };
    resA_run<2, 1, 1>(g_x1 + n * 128, 384, m0, M, Wj, bj, oj, osj);
}

__global__ __launch_bounds__(256, 2) void k_g_ffn2(
    const float* __restrict__ B2,
    const float* __restrict__ fg, const float* __restrict__ fb, int M)
{
    const int n = blockIdx.y;
    mma_gemm<3, 0, 0>(g_h + n * 256, 768, g_wtf + WOFF_FFN2 + n * 128 * 256, 256,
                      B2 + n * 128, fg + n * 128, fb + n * 128, nullptr,
                      g_x1 + n * 128, 384, g_x2 + n * 128, 384, blockIdx.x * 128, M);
}

// ---------------- weight tf32 pre-convert (single launch) ----------------
__global__ __launch_bounds__(256) void k_cvt_all(
    const float* __restrict__ s0, const float* __restrict__ s1,
    const float* __restrict__ s2, const float* __restrict__ s3,
    const float* __restrict__ s4, const float* __restrict__ s5)
{
    const int i = blockIdx.x * 256 + threadIdx.x;
    if (i >= 147456) return;
    const float* src; int base;
    if      (i <  40960) { src = s0; base = 0;      }
    else if (i <  49152) { src = s1; base = 40960;  }
    else if (i <  86016) { src = s2; base = 49152;  }
    else if (i <  98304) { src = s3; base = 86016;  }
    else if (i < 122880) { src = s4; base = 98304;  }
    else                 { src = s5; base = 122880; }
    const float4 v = ((const float4*)src)[i - base];
    float4 o;
    o.x = tfr(v.x); o.y = tfr(v.y); o.z = tfr(v.z); o.w = tfr(v.w);
    ((float4*)g_wtf)[i] = o;
}

// ---------------- Attention + gate ----------------

__global__ __launch_bounds__(256) void k_attn(int M)
{
    const int rid = blockIdx.x * 8 + (threadIdx.x >> 5);
    if (rid >= M * 3) return;
    const int lane = threadIdx.x & 31;
    const int d4 = lane * 4;
    const long qb = (long)rid * 128;
    const long kb = (long)rid * 256;

    const float4 q4  = *(const float4*)(g_q + qb + d4);
    const float4 k04 = *(const float4*)(g_k + kb + d4);
    const float4 k14 = *(const float4*)(g_k + kb + 128 + d4);
    const float4 v04 = *(const float4*)(g_v + kb + d4);
    const float4 v14 = *(const float4*)(g_v + kb + 128 + d4);

    float s0 = q4.x * k04.x + q4.y * k04.y + q4.z * k04.z + q4.w * k04.w;
    float s1 = q4.x * k14.x + q4.y * k14.y + q4.z * k14.z + q4.w * k14.w;
#pragma unroll
    for (int o = 4; o; o >>= 1) {
        s0 += __shfl_xor_sync(0xffffffffu, s0, o);
        s1 += __shfl_xor_sync(0xffffffffu, s1, o);
    }
    const float scale = 0.17677669529663687f;
    s0 *= scale; s1 *= scale;
    const float mx = fmaxf(s0, s1);
    const float e0 = expf(s0 - mx), e1 = expf(s1 - mx);
    const float inv = 1.0f / (e0 + e1);
    const float w0 = e0 * inv, w1 = e1 * inv;

    float4 o4;   // tf32-rounded: feeds outproj GEMM as A
    o4.x = tfr(w0 * v04.x + w1 * v14.x);
    o4.y = tfr(w0 * v04.y + w1 * v14.y);
    o4.z = tfr(w0 * v04.z + w1 * v14.z);
    o4.w = tfr(w0 * v04.w + w1 * v14.w);
    *(float4*)(g_o + qb + d4) = o4;
}

__global__ __launch_bounds__(256) void k_gate(
    const float* __restrict__ gw, const float* __restrict__ gb,
    float* __restrict__ out, int M)
{
    const int b = blockIdx.x * 8 + (threadIdx.x >> 5);
    if (b >= M) return;
    const int lane = threadIdx.x & 31;
    const float* xr = g_x2 + (long)b * 384;
    float l0 = 0.f, l1 = 0.f, l2 = 0.f;
#pragma unroll
    for (int j = 0; j < 12; ++j) {
        const int idx = lane + 32 * j;
        const float x = xr[idx];
        l0 += x * gw[idx];
        l1 += x * gw[384 + idx];
        l2 += x * gw[768 + idx];
    }
#pragma unroll
    for (int o = 16; o; o >>= 1) {
        l0 += __shfl_xor_sync(0xffffffffu, l0, o);
        l1 += __shfl_xor_sync(0xffffffffu, l1, o);
        l2 += __shfl_xor_sync(0xffffffffu, l2, o);
    }
    l0 += gb[0]; l1 += gb[1]; l2 += gb[2];
    const float mx = fmaxf(l0, fmaxf(l1, l2));
    const float e0 = expf(l0 - mx), e1 = expf(l1 - mx), e2 = expf(l2 - mx);
    const float inv = 1.0f / (e0 + e1 + e2);
    const float w0 = e0 * inv, w1 = e1 * inv, w2 = e2 * inv;
#pragma unroll
    for (int j = 0; j < 4; ++j) {
        const int d = lane + 32 * j;
        out[(long)b * 128 + d] = w0 * xr[d] + w1 * xr[128 + d] + w2 * xr[256 + d];
    }
}

// ---------------------------------------------------------------------------

extern "C" void kernel_launch(void* const* d_in, const int* in_sizes, int n_in,
                              void* d_out, int out_size)
{
    const float* x_spatial   = (const float*)d_in[0];
    const float* x_gradient  = (const float*)d_in[1];
    const float* x_frequency = (const float*)d_in[2];
    const float* w_spatial   = (const float*)d_in[3];
    const float* w_gf        = (const float*)d_in[4];
    const float* proj_b      = (const float*)d_in[5];
    const float* proj_ln_g   = (const float*)d_in[6];
    const float* proj_ln_b   = (const float*)d_in[7];
    const float* mod_emb     = (const float*)d_in[8];
    const float* in_w        = (const float*)d_in[9];
    const float* in_b        = (const float*)d_in[10];
    const float* out_w       = (const float*)d_in[11];
    const float* out_b       = (const float*)d_in[12];
    const float* attn_g      = (const float*)d_in[13];
    const float* attn_b      = (const float*)d_in[14];
    const float* w1          = (const float*)d_in[15];
    const float* b1          = (const float*)d_in[16];
    const float* w2          = (const float*)d_in[17];
    const float* b2          = (const float*)d_in[18];
    const float* ffn_g       = (const float*)d_in[19];
    const float* ffn_b       = (const float*)d_in[20];
    const float* gate_w      = (const float*)d_in[21];
    const float* gate_b      = (const float*)d_in[22];
    float* out = (float*)d_out;

    static int smem_set = 0;
    if (!smem_set) {
        cudaFuncSetAttribute(k_g_proj,    cudaFuncAttributeMaxDynamicSharedMemorySize, GSMEM);
        cudaFuncSetAttribute(k_g_qkv,     cudaFuncAttributeMaxDynamicSharedMemorySize, QSMEM);
        cudaFuncSetAttribute(k_g_outproj, cudaFuncAttributeMaxDynamicSharedMemorySize, GSMEM);
        cudaFuncSetAttribute(k_g_ffn1,    cudaFuncAttributeMaxDynamicSharedMemorySize, QSMEM);
        cudaFuncSetAttribute(k_g_ffn2,    cudaFuncAttributeMaxDynamicSharedMemorySize, GSMEM);
        smem_set = 1;
    }

    int B = in_sizes[0] / 1280;
    if (B > MAXB) B = MAXB;
    const int gm = (B + 127) / 128;
    const int R  = B * 3;

    k_cvt_all<<<(147456 + 255) / 256, 256>>>(w_spatial, w_gf, in_w, out_w, w1, w2);

    k_g_proj<<<dim3(gm, 3), 256, GSMEM>>>(x_spatial, x_gradient, x_frequency,
                                          proj_b, proj_ln_g, proj_ln_b, mod_emb, B);
    k_g_qkv<<<dim3(gm, 3), 256, QSMEM>>>(in_b, B);
    k_attn<<<(R + 7) / 8, 256>>>(B);
    k_g_outproj<<<dim3(gm, 3), 256, GSMEM>>>(out_b, attn_g, attn_b, B);
    k_g_ffn1<<<dim3(gm, 3), 256, QSMEM>>>(b1, B);
    k_g_ffn2<<<dim3(gm, 3), 256, GSMEM>>>(b2, ffn_g, ffn_b, B);
    k_gate<<<(B + 7) / 8, 256>>>(gate_w, gate_b, out, B);
}